// round 12
// baseline (speedup 1.0000x reference)
#include <cuda_runtime.h>
#include <math.h>

#define NN 50000
#define NE 800000
#define MB 148           // mega blocks: one per SM, all co-resident
#define MT 512           // mega threads per block
#define GB 391           // gemm blocks: 128-node tile each; 391*128 = 50048 >= NN

// ---- device scratch ----
__device__ float4 g_h[NN * 16];     // h = x@W, [NN,64] as float4
__device__ float  g_s1[NN];         // dot(h[n], a[:64])
__device__ float  g_s2[NN];         // dot(h[n], a[64:])
__device__ int    g_cnt[NN];        // in-degree
__device__ int    g_off[NN];        // exclusive prefix (CSR row start)
__device__ int    g_cur[NN];        // running cursor for sort
__device__ int2   g_srt[NE];        // sorted records: (src node j, expv bits)
__device__ int    g_bsum[MB];       // per-block sums
__device__ int    g_bbase[MB];      // exclusive scan of block sums
__device__ float  g_sum;            // sum of exp(logits)
__device__ unsigned g_bar[4];       // grid-barrier arrival counters

// ---------------- K1: h = x@W + per-node scores ----------------
// thread = (node pair, column quarter): 2 nodes x 16 cols, 16 f32x2 accs (32 regs).
// 391 blocks x 256 thr, 3 blocks/SM -> 24 warps/SM, single wave, 14% imbalance.
__global__ void __launch_bounds__(256, 3)
k_gemm(const float* __restrict__ x,
       const float* __restrict__ W,
       const float* __restrict__ attn) {
    __shared__ ulonglong2 Ws2[128 * 16];   // W[k][0:64]: [k*16 + q4*4 + c]
    __shared__ float aws[128];
    const int t = threadIdx.x;
    const int gt = blockIdx.x * 256 + t;

    // prologue: reset per-replay state (runs before k_mega in stream order)
    for (int i = gt; i < NN; i += GB * 256) g_cnt[i] = 0;
    if (gt == 0) {
        g_sum = 0.f;
        g_bar[0] = 0; g_bar[1] = 0; g_bar[2] = 0; g_bar[3] = 0;
    }

    {
        const float4* W4 = (const float4*)W;
        float4* Ws4 = (float4*)Ws2;
        for (int i = t; i < 2048; i += 256) Ws4[i] = W4[i];
        if (t < 128) aws[t] = attn[t];
    }
    __syncthreads();

    const int pair = t >> 2;          // 0..63 node-pair slot
    const int q4 = t & 3;             // column quarter: cols [q4*16, q4*16+16)
    const int n0 = blockIdx.x * 128 + pair * 2;
    if (n0 >= NN) return;
    const int n1 = n0 + 1;
    const size_t r0 = (size_t)n0;
    const size_t r1 = (size_t)((n1 < NN) ? n1 : n0);

    unsigned long long accA[8], accB[8];   // 16 cols per node as f32x2
    #pragma unroll
    for (int c = 0; c < 8; c++) { accA[c] = 0ull; accB[c] = 0ull; }

    const float4* x4 = (const float4*)x;
    #pragma unroll 1
    for (int k4 = 0; k4 < 32; k4++) {
        float4 xa = x4[r0 * 32 + k4];
        float4 xb = x4[r1 * 32 + k4];
        #pragma unroll
        for (int s = 0; s < 4; s++) {
            float fa = (s == 0) ? xa.x : (s == 1) ? xa.y : (s == 2) ? xa.z : xa.w;
            float fb = (s == 0) ? xb.x : (s == 1) ? xb.y : (s == 2) ? xb.z : xb.w;
            unsigned long long pa, pb;
            asm("mov.b64 %0, {%1, %1};" : "=l"(pa) : "f"(fa));
            asm("mov.b64 %0, {%1, %1};" : "=l"(pb) : "f"(fb));
            const ulonglong2* wk = Ws2 + (k4 * 4 + s) * 16 + q4 * 4;
            #pragma unroll
            for (int c = 0; c < 4; c++) {
                ulonglong2 wv = wk[c];
                asm("fma.rn.f32x2 %0, %1, %2, %0;" : "+l"(accA[2*c])   : "l"(pa), "l"(wv.x));
                asm("fma.rn.f32x2 %0, %1, %2, %0;" : "+l"(accA[2*c+1]) : "l"(pa), "l"(wv.y));
                asm("fma.rn.f32x2 %0, %1, %2, %0;" : "+l"(accB[2*c])   : "l"(pb), "l"(wv.x));
                asm("fma.rn.f32x2 %0, %1, %2, %0;" : "+l"(accB[2*c+1]) : "l"(pb), "l"(wv.y));
            }
        }
    }

    const int cb = q4 * 16;           // this thread's column base
    float p1a = 0.f, p2a = 0.f, p1b = 0.f, p2b = 0.f;
    #pragma unroll
    for (int q = 0; q < 4; q++) {
        float4 v;
        asm("mov.b64 {%0, %1}, %2;" : "=f"(v.x), "=f"(v.y) : "l"(accA[2*q]));
        asm("mov.b64 {%0, %1}, %2;" : "=f"(v.z), "=f"(v.w) : "l"(accA[2*q+1]));
        g_h[r0 * 16 + q4 * 4 + q] = v;
        p1a += v.x*aws[cb+4*q] + v.y*aws[cb+4*q+1] + v.z*aws[cb+4*q+2] + v.w*aws[cb+4*q+3];
        p2a += v.x*aws[64+cb+4*q] + v.y*aws[64+cb+4*q+1] + v.z*aws[64+cb+4*q+2] + v.w*aws[64+cb+4*q+3];
    }
    if (n1 < NN) {
        #pragma unroll
        for (int q = 0; q < 4; q++) {
            float4 v;
            asm("mov.b64 {%0, %1}, %2;" : "=f"(v.x), "=f"(v.y) : "l"(accB[2*q]));
            asm("mov.b64 {%0, %1}, %2;" : "=f"(v.z), "=f"(v.w) : "l"(accB[2*q+1]));
            g_h[(size_t)n1 * 16 + q4 * 4 + q] = v;
            p1b += v.x*aws[cb+4*q] + v.y*aws[cb+4*q+1] + v.z*aws[cb+4*q+2] + v.w*aws[cb+4*q+3];
            p2b += v.x*aws[64+cb+4*q] + v.y*aws[64+cb+4*q+1] + v.z*aws[64+cb+4*q+2] + v.w*aws[64+cb+4*q+3];
        }
    }
    // combine 4 column quarters (lanes 4k..4k+3 hold the same node pair)
    #pragma unroll
    for (int o = 1; o < 4; o <<= 1) {
        p1a += __shfl_xor_sync(0xffffffffu, p1a, o);
        p2a += __shfl_xor_sync(0xffffffffu, p2a, o);
        p1b += __shfl_xor_sync(0xffffffffu, p1b, o);
        p2b += __shfl_xor_sync(0xffffffffu, p2b, o);
    }
    if (q4 == 0) {
        g_s1[n0] = p1a; g_s2[n0] = p2a;
        if (n1 < NN) { g_s1[n1] = p1b; g_s2[n1] = p2b; }
    }
}

// ---------------- grid barrier (all MB blocks co-resident) ----------------
__device__ __forceinline__ void gridsync(int p) {
    __syncthreads();
    if (threadIdx.x == 0) {
        __threadfence();
        atomicAdd(&g_bar[p], 1u);
        while (atomicAdd(&g_bar[p], 0u) < (unsigned)MB) { }
        __threadfence();
    }
    __syncthreads();
}

// ---------------- K2: fused count + scan + sort (persistent, 148 blocks) ----------------
__global__ void __launch_bounds__(MT)
k_mega(const int* __restrict__ eidx) {
    __shared__ int sm[MT];
    __shared__ float wr[MT / 32];
    const int b = blockIdx.x, t = threadIdx.x;
    const int gt = b * MT + t;
    const int nth = MB * MT;

    // phase A: destination histogram
    for (int e = gt; e < NE; e += nth)
        atomicAdd(&g_cnt[__ldg(eidx + e)], 1);
    gridsync(0);

    // phase B1: local exclusive scan of this block's MT nodes
    const int n = gt;
    int v = (n < NN) ? __ldcg(&g_cnt[n]) : 0;
    sm[t] = v;
    __syncthreads();
    #pragma unroll
    for (int off = 1; off < MT; off <<= 1) {
        int add = (t >= off) ? sm[t - off] : 0;
        __syncthreads();
        sm[t] += add;
        __syncthreads();
    }
    if (t == MT - 1) g_bsum[b] = sm[MT - 1];
    const int local_ex = sm[t] - v;
    gridsync(1);

    // phase B2: block 0 scans the 148 block sums
    if (b == 0) {
        int vv = (t < MB) ? __ldcg(&g_bsum[t]) : 0;
        sm[t] = vv;
        __syncthreads();
        #pragma unroll
        for (int off = 1; off < MT; off <<= 1) {
            int add = (t >= off) ? sm[t - off] : 0;
            __syncthreads();
            sm[t] += add;
            __syncthreads();
        }
        if (t < MB) g_bbase[t] = sm[t] - vv;
    }
    gridsync(2);

    // phase B3: write CSR offsets + cursors
    if (n < NN) {
        int o = __ldcg(&g_bbase[b]) + local_ex;
        g_off[n] = o;
        g_cur[n] = o;
    }
    gridsync(3);

    // phase C: fused expv + counting-sort + global sum
    float lsum = 0.f;
    for (int e = gt; e < NE; e += nth) {
        int i = __ldg(eidx + e);
        int j = __ldg(eidx + NE + e);
        float l = g_s1[i] + g_s2[j];
        l = (l > 0.f) ? l : 0.2f * l;       // leaky_relu 0.2
        float ex = __expf(l);
        lsum += ex;
        int pos = atomicAdd(&g_cur[i], 1);
        g_srt[pos] = make_int2(j, __float_as_int(ex));
    }
    #pragma unroll
    for (int o = 16; o > 0; o >>= 1) lsum += __shfl_down_sync(0xffffffffu, lsum, o);
    int w = t >> 5, lane = t & 31;
    if (lane == 0) wr[w] = lsum;
    __syncthreads();
    if (w == 0) {
        float s = (lane < MT / 32) ? wr[lane] : 0.f;
        #pragma unroll
        for (int o = 8; o > 0; o >>= 1) s += __shfl_down_sync(0xffffffffu, s, o);
        if (lane == 0) atomicAdd(&g_sum, s);
    }
}

// ---------------- K3: per-node gather (1 warp/node, 2 records in flight) ----------------
__global__ void k_gather(float* __restrict__ out) {
    int gt = blockIdx.x * blockDim.x + threadIdx.x;
    int lane = threadIdx.x & 31;
    int n = gt >> 5;
    if (n >= NN) return;
    int l16 = lane & 15;
    int sub = lane >> 4;

    float inv = 1.0f / g_sum;
    int beg = g_off[n];
    int cnt = g_cnt[n];

    float4 acc = make_float4(0.f, 0.f, 0.f, 0.f);
    int k = sub;
    int2 rec = (k < cnt) ? __ldg(&g_srt[beg + k]) : make_int2(0, 0);
    while (k < cnt) {
        int2 cur = rec;
        int kn = k + 2;
        if (kn < cnt) rec = __ldg(&g_srt[beg + kn]);
        float ex = __int_as_float(cur.y);
        float4 hv = g_h[(size_t)cur.x * 16 + l16];
        acc.x += hv.x * ex; acc.y += hv.y * ex;
        acc.z += hv.z * ex; acc.w += hv.w * ex;
        k = kn;
    }
    acc.x += __shfl_xor_sync(0xffffffffu, acc.x, 16);
    acc.y += __shfl_xor_sync(0xffffffffu, acc.y, 16);
    acc.z += __shfl_xor_sync(0xffffffffu, acc.z, 16);
    acc.w += __shfl_xor_sync(0xffffffffu, acc.w, 16);
    acc.x *= inv; acc.y *= inv; acc.z *= inv; acc.w *= inv;

    float4* o = (float4*)out + (size_t)n * 128;
    #pragma unroll
    for (int q = 0; q < 4; q++) o[lane + 32 * q] = acc;
}

extern "C" void kernel_launch(void* const* d_in, const int* in_sizes, int n_in,
                              void* d_out, int out_size) {
    const float* x    = (const float*)d_in[0];
    const int*   eidx = (const int*)d_in[1];
    const float* W    = (const float*)d_in[2];
    const float* attn = (const float*)d_in[3];
    float* out = (float*)d_out;

    k_gemm<<<GB, 256>>>(x, W, attn);
    k_mega<<<MB, MT>>>(eidx);
    k_gather<<<(NN * 32 + 255) / 256, 256>>>(out);
}

// round 14
// speedup vs baseline: 1.2619x; 1.2619x over previous
#include <cuda_runtime.h>
#include <math.h>

#define NN 50000
#define NE 800000
#define MB 148           // mega blocks: one per SM, all co-resident
#define MT 512           // mega threads per block
#define GB 391           // gemm blocks: 128-node tile each; 391*128 = 50048 >= NN

// ---- device scratch ----
__device__ float4 g_h[NN * 16];     // h = x@W, [NN,64] as float4
__device__ float  g_s1[NN];         // dot(h[n], a[:64])
__device__ float  g_s2[NN];         // dot(h[n], a[64:])
__device__ int    g_cnt[NN];        // in-degree
__device__ int    g_off[NN];        // exclusive prefix (CSR row start)
__device__ int    g_cur[NN];        // running cursor for sort
__device__ int2   g_srt[NE];        // sorted records: (src node j, expv bits)
__device__ int    g_bsum[MB];       // per-block sums
__device__ int    g_bbase[MB];      // exclusive scan of block sums
__device__ float  g_sum;            // sum of exp(logits)
__device__ unsigned g_bar[4];       // grid-barrier arrival counters

// ---------------- K1: h = x@W + per-node scores ----------------
// thread = (node pair, column quarter): 2 nodes x 16 cols, 16 f32x2 accs.
// W smem stored chunk-transposed [k*16 + c*4 + q4] -> conflict-free LDS.
// x software-pipelined (next k4 prefetched) -> load latency hidden.
__global__ void __launch_bounds__(256, 3)
k_gemm(const float* __restrict__ x,
       const float* __restrict__ W,
       const float* __restrict__ attn) {
    __shared__ ulonglong2 Ws2[128 * 16];   // [k*16 + c*4 + q4]
    __shared__ float aws[128];
    const int t = threadIdx.x;
    const int gt = blockIdx.x * 256 + t;

    // prologue: reset per-replay state (runs before k_mega in stream order)
    for (int i = gt; i < NN; i += GB * 256) g_cnt[i] = 0;
    if (gt == 0) {
        g_sum = 0.f;
        g_bar[0] = 0; g_bar[1] = 0; g_bar[2] = 0; g_bar[3] = 0;
    }

    {
        const float4* W4 = (const float4*)W;
        float4* Ws4 = (float4*)Ws2;
        // physical [k*16 + c*4 + q] <- logical chunk (k, q*4 + c)
        for (int p = t; p < 2048; p += 256) {
            int k = p >> 4, j = p & 15, c = j >> 2, q = j & 3;
            Ws4[p] = W4[k * 16 + q * 4 + c];
        }
        if (t < 128) aws[t] = attn[t];
    }
    __syncthreads();

    const int pair = t >> 2;          // 0..63 node-pair slot
    const int q4 = t & 3;             // column quarter: cols [q4*16, q4*16+16)
    const int n0 = blockIdx.x * 128 + pair * 2;
    if (n0 >= NN) return;
    const int n1 = n0 + 1;
    const size_t r0 = (size_t)n0;
    const size_t r1 = (size_t)((n1 < NN) ? n1 : n0);

    unsigned long long accA[8], accB[8];   // 16 cols per node as f32x2
    #pragma unroll
    for (int c = 0; c < 8; c++) { accA[c] = 0ull; accB[c] = 0ull; }

    const float4* x4 = (const float4*)x;
    float4 xa = x4[r0 * 32];
    float4 xb = x4[r1 * 32];
    #pragma unroll 1
    for (int k4 = 0; k4 < 32; k4++) {
        // prefetch next iteration's x before consuming this one's
        int kn = (k4 < 31) ? (k4 + 1) : 31;
        float4 nxa = x4[r0 * 32 + kn];
        float4 nxb = x4[r1 * 32 + kn];
        #pragma unroll
        for (int s = 0; s < 4; s++) {
            float fa = (s == 0) ? xa.x : (s == 1) ? xa.y : (s == 2) ? xa.z : xa.w;
            float fb = (s == 0) ? xb.x : (s == 1) ? xb.y : (s == 2) ? xb.z : xb.w;
            unsigned long long pa, pb;
            asm("mov.b64 %0, {%1, %1};" : "=l"(pa) : "f"(fa));
            asm("mov.b64 %0, {%1, %1};" : "=l"(pb) : "f"(fb));
            const ulonglong2* wk = Ws2 + (k4 * 4 + s) * 16 + q4;   // stride 4 per c
            #pragma unroll
            for (int c = 0; c < 4; c++) {
                ulonglong2 wv = wk[c * 4];
                asm("fma.rn.f32x2 %0, %1, %2, %0;" : "+l"(accA[2*c])   : "l"(pa), "l"(wv.x));
                asm("fma.rn.f32x2 %0, %1, %2, %0;" : "+l"(accA[2*c+1]) : "l"(pa), "l"(wv.y));
                asm("fma.rn.f32x2 %0, %1, %2, %0;" : "+l"(accB[2*c])   : "l"(pb), "l"(wv.x));
                asm("fma.rn.f32x2 %0, %1, %2, %0;" : "+l"(accB[2*c+1]) : "l"(pb), "l"(wv.y));
            }
        }
        xa = nxa; xb = nxb;
    }

    const int cb = q4 * 16;           // this thread's column base
    float p1a = 0.f, p2a = 0.f, p1b = 0.f, p2b = 0.f;
    #pragma unroll
    for (int q = 0; q < 4; q++) {
        float4 v;
        asm("mov.b64 {%0, %1}, %2;" : "=f"(v.x), "=f"(v.y) : "l"(accA[2*q]));
        asm("mov.b64 {%0, %1}, %2;" : "=f"(v.z), "=f"(v.w) : "l"(accA[2*q+1]));
        g_h[r0 * 16 + q4 * 4 + q] = v;
        p1a += v.x*aws[cb+4*q] + v.y*aws[cb+4*q+1] + v.z*aws[cb+4*q+2] + v.w*aws[cb+4*q+3];
        p2a += v.x*aws[64+cb+4*q] + v.y*aws[64+cb+4*q+1] + v.z*aws[64+cb+4*q+2] + v.w*aws[64+cb+4*q+3];
    }
    if (n1 < NN) {
        #pragma unroll
        for (int q = 0; q < 4; q++) {
            float4 v;
            asm("mov.b64 {%0, %1}, %2;" : "=f"(v.x), "=f"(v.y) : "l"(accB[2*q]));
            asm("mov.b64 {%0, %1}, %2;" : "=f"(v.z), "=f"(v.w) : "l"(accB[2*q+1]));
            g_h[(size_t)n1 * 16 + q4 * 4 + q] = v;
            p1b += v.x*aws[cb+4*q] + v.y*aws[cb+4*q+1] + v.z*aws[cb+4*q+2] + v.w*aws[cb+4*q+3];
            p2b += v.x*aws[64+cb+4*q] + v.y*aws[64+cb+4*q+1] + v.z*aws[64+cb+4*q+2] + v.w*aws[64+cb+4*q+3];
        }
    }
    // combine 4 column quarters (lanes 4k..4k+3 hold the same node pair)
    #pragma unroll
    for (int o = 1; o < 4; o <<= 1) {
        p1a += __shfl_xor_sync(0xffffffffu, p1a, o);
        p2a += __shfl_xor_sync(0xffffffffu, p2a, o);
        p1b += __shfl_xor_sync(0xffffffffu, p1b, o);
        p2b += __shfl_xor_sync(0xffffffffu, p2b, o);
    }
    if (q4 == 0) {
        g_s1[n0] = p1a; g_s2[n0] = p2a;
        if (n1 < NN) { g_s1[n1] = p1b; g_s2[n1] = p2b; }
    }
}

// ---------------- grid barrier (all MB blocks co-resident) ----------------
__device__ __forceinline__ void gridsync(int p) {
    __syncthreads();
    if (threadIdx.x == 0) {
        __threadfence();
        atomicAdd(&g_bar[p], 1u);
        while (atomicAdd(&g_bar[p], 0u) < (unsigned)MB) { }
        __threadfence();
    }
    __syncthreads();
}

// ---------------- K2: fused count + scan + sort (persistent, 148 blocks) ----------------
__global__ void __launch_bounds__(MT)
k_mega(const int* __restrict__ eidx) {
    __shared__ int sm[MT];
    __shared__ float wr[MT / 32];
    const int b = blockIdx.x, t = threadIdx.x;
    const int gt = b * MT + t;
    const int nth = MB * MT;

    // phase A: destination histogram
    for (int e = gt; e < NE; e += nth)
        atomicAdd(&g_cnt[__ldg(eidx + e)], 1);
    gridsync(0);

    // phase B1: local exclusive scan of this block's MT nodes
    const int n = gt;
    int v = (n < NN) ? __ldcg(&g_cnt[n]) : 0;
    sm[t] = v;
    __syncthreads();
    #pragma unroll
    for (int off = 1; off < MT; off <<= 1) {
        int add = (t >= off) ? sm[t - off] : 0;
        __syncthreads();
        sm[t] += add;
        __syncthreads();
    }
    if (t == MT - 1) g_bsum[b] = sm[MT - 1];
    const int local_ex = sm[t] - v;
    gridsync(1);

    // phase B2: block 0 scans the 148 block sums
    if (b == 0) {
        int vv = (t < MB) ? __ldcg(&g_bsum[t]) : 0;
        sm[t] = vv;
        __syncthreads();
        #pragma unroll
        for (int off = 1; off < MT; off <<= 1) {
            int add = (t >= off) ? sm[t - off] : 0;
            __syncthreads();
            sm[t] += add;
            __syncthreads();
        }
        if (t < MB) g_bbase[t] = sm[t] - vv;
    }
    gridsync(2);

    // phase B3: write CSR offsets + cursors
    if (n < NN) {
        int o = __ldcg(&g_bbase[b]) + local_ex;
        g_off[n] = o;
        g_cur[n] = o;
    }
    gridsync(3);

    // phase C: fused expv + counting-sort + global sum
    float lsum = 0.f;
    for (int e = gt; e < NE; e += nth) {
        int i = __ldg(eidx + e);
        int j = __ldg(eidx + NE + e);
        float l = g_s1[i] + g_s2[j];
        l = (l > 0.f) ? l : 0.2f * l;       // leaky_relu 0.2
        float ex = __expf(l);
        lsum += ex;
        int pos = atomicAdd(&g_cur[i], 1);
        g_srt[pos] = make_int2(j, __float_as_int(ex));
    }
    #pragma unroll
    for (int o = 16; o > 0; o >>= 1) lsum += __shfl_down_sync(0xffffffffu, lsum, o);
    int w = t >> 5, lane = t & 31;
    if (lane == 0) wr[w] = lsum;
    __syncthreads();
    if (w == 0) {
        float s = (lane < MT / 32) ? wr[lane] : 0.f;
        #pragma unroll
        for (int o = 8; o > 0; o >>= 1) s += __shfl_down_sync(0xffffffffu, s, o);
        if (lane == 0) atomicAdd(&g_sum, s);
    }
}

// ---------------- K3: per-node gather (1 warp/node, 2 records in flight) ----------------
__global__ void k_gather(float* __restrict__ out) {
    int gt = blockIdx.x * blockDim.x + threadIdx.x;
    int lane = threadIdx.x & 31;
    int n = gt >> 5;
    if (n >= NN) return;
    int l16 = lane & 15;
    int sub = lane >> 4;

    float inv = 1.0f / g_sum;
    int beg = g_off[n];
    int cnt = g_cnt[n];

    float4 acc = make_float4(0.f, 0.f, 0.f, 0.f);
    int k = sub;
    int2 rec = (k < cnt) ? __ldg(&g_srt[beg + k]) : make_int2(0, 0);
    while (k < cnt) {
        int2 cur = rec;
        int kn = k + 2;
        if (kn < cnt) rec = __ldg(&g_srt[beg + kn]);
        float ex = __int_as_float(cur.y);
        float4 hv = g_h[(size_t)cur.x * 16 + l16];
        acc.x += hv.x * ex; acc.y += hv.y * ex;
        acc.z += hv.z * ex; acc.w += hv.w * ex;
        k = kn;
    }
    acc.x += __shfl_xor_sync(0xffffffffu, acc.x, 16);
    acc.y += __shfl_xor_sync(0xffffffffu, acc.y, 16);
    acc.z += __shfl_xor_sync(0xffffffffu, acc.z, 16);
    acc.w += __shfl_xor_sync(0xffffffffu, acc.w, 16);
    acc.x *= inv; acc.y *= inv; acc.z *= inv; acc.w *= inv;

    float4* o = (float4*)out + (size_t)n * 128;
    #pragma unroll
    for (int q = 0; q < 4; q++) o[lane + 32 * q] = acc;
}

extern "C" void kernel_launch(void* const* d_in, const int* in_sizes, int n_in,
                              void* d_out, int out_size) {
    const float* x    = (const float*)d_in[0];
    const int*   eidx = (const int*)d_in[1];
    const float* W    = (const float*)d_in[2];
    const float* attn = (const float*)d_in[3];
    float* out = (float*)d_out;

    k_gemm<<<GB, 256>>>(x, W, attn);
    k_mega<<<MB, MT>>>(eidx);
    k_gather<<<(NN * 32 + 255) / 256, 256>>>(out);
}

// round 15
// speedup vs baseline: 1.2950x; 1.0262x over previous
#include <cuda_runtime.h>
#include <math.h>

#define NN 50000
#define NE 800000
#define MB 148           // mega blocks: one per SM, all co-resident
#define MT 512           // mega threads per block
#define GB 391           // gemm blocks: 128-node tile each; 391*128 = 50048 >= NN

// ---- device scratch ----
__device__ float4 g_h[NN * 16];     // h = x@W, [NN,64] as float4
__device__ float  g_s1[NN];         // dot(h[n], a[:64])
__device__ float  g_s2[NN];         // dot(h[n], a[64:])
__device__ int    g_cnt[NN];        // in-degree
__device__ int    g_off[NN];        // exclusive prefix (CSR row start)
__device__ int    g_cur[NN];        // running cursor for sort
__device__ int2   g_srt[NE];        // sorted records: (src node j, expv bits)
__device__ int    g_bsum[MB];       // per-block sums
__device__ int    g_bbase[MB];      // exclusive scan of block sums
__device__ float  g_sum;            // sum of exp(logits)
__device__ unsigned g_bar[4];       // grid-barrier arrival counters

// ---------------- K1: h = x@W + per-node scores ----------------
// thread = (node pair, column half): 2 nodes x 32 cols, 32 f32x2 accs (64 regs).
// 128-thread blocks, launch_bounds(128,4) -> 4 blocks/SM = 16 warps/SM.
// W smem chunk-transposed [k*16 + c*2 + half] -> bank-disjoint halves (N=1).
__global__ void __launch_bounds__(128, 4)
k_gemm(const float* __restrict__ x,
       const float* __restrict__ W,
       const float* __restrict__ attn) {
    __shared__ ulonglong2 Ws2[128 * 16];   // [k*16 + c*2 + half]
    __shared__ float aws[128];
    const int t = threadIdx.x;
    const int gt = blockIdx.x * 128 + t;

    // prologue: reset per-replay state (runs before k_mega in stream order)
    for (int i = gt; i < NN; i += GB * 128) g_cnt[i] = 0;
    if (gt == 0) {
        g_sum = 0.f;
        g_bar[0] = 0; g_bar[1] = 0; g_bar[2] = 0; g_bar[3] = 0;
    }

    {
        const float4* W4 = (const float4*)W;
        float4* Ws4 = (float4*)Ws2;
        // physical [k*16 + c*2 + half] <- logical chunk (k, half*8 + c)
        for (int p = t; p < 2048; p += 128) {
            int k = p >> 4, j = p & 15, c = j >> 1, hf = j & 1;
            Ws4[p] = W4[k * 16 + hf * 8 + c];
        }
        if (t < 128) aws[t] = attn[t];
    }
    __syncthreads();

    const int slot = t >> 1;          // 0..63 node-pair slot
    const int half = t & 1;           // column half: cols [half*32, half*32+32)
    const int n0 = blockIdx.x * 128 + slot * 2;
    if (n0 >= NN) return;
    const int n1 = n0 + 1;
    const size_t r0 = (size_t)n0;
    const size_t r1 = (size_t)((n1 < NN) ? n1 : n0);

    unsigned long long accA[16], accB[16];   // 32 cols per node as f32x2
    #pragma unroll
    for (int c = 0; c < 16; c++) { accA[c] = 0ull; accB[c] = 0ull; }

    const float4* x4 = (const float4*)x;
    float4 xa = x4[r0 * 32];
    float4 xb = x4[r1 * 32];
    #pragma unroll 1
    for (int k4 = 0; k4 < 32; k4++) {
        // prefetch next iteration's x before consuming this one's
        int kn = (k4 < 31) ? (k4 + 1) : 31;
        float4 nxa = x4[r0 * 32 + kn];
        float4 nxb = x4[r1 * 32 + kn];
        #pragma unroll
        for (int s = 0; s < 4; s++) {
            float fa = (s == 0) ? xa.x : (s == 1) ? xa.y : (s == 2) ? xa.z : xa.w;
            float fb = (s == 0) ? xb.x : (s == 1) ? xb.y : (s == 2) ? xb.z : xb.w;
            unsigned long long pa, pb;
            asm("mov.b64 %0, {%1, %1};" : "=l"(pa) : "f"(fa));
            asm("mov.b64 %0, {%1, %1};" : "=l"(pb) : "f"(fb));
            const ulonglong2* wk = Ws2 + (k4 * 4 + s) * 16 + half;   // stride 2 per c
            #pragma unroll
            for (int c = 0; c < 8; c++) {
                ulonglong2 wv = wk[c * 2];
                asm("fma.rn.f32x2 %0, %1, %2, %0;" : "+l"(accA[2*c])   : "l"(pa), "l"(wv.x));
                asm("fma.rn.f32x2 %0, %1, %2, %0;" : "+l"(accA[2*c+1]) : "l"(pa), "l"(wv.y));
                asm("fma.rn.f32x2 %0, %1, %2, %0;" : "+l"(accB[2*c])   : "l"(pb), "l"(wv.x));
                asm("fma.rn.f32x2 %0, %1, %2, %0;" : "+l"(accB[2*c+1]) : "l"(pb), "l"(wv.y));
            }
        }
        xa = nxa; xb = nxb;
    }

    const int cb = half * 32;         // this thread's column base
    float p1a = 0.f, p2a = 0.f, p1b = 0.f, p2b = 0.f;
    #pragma unroll
    for (int q = 0; q < 8; q++) {
        float4 v;
        asm("mov.b64 {%0, %1}, %2;" : "=f"(v.x), "=f"(v.y) : "l"(accA[2*q]));
        asm("mov.b64 {%0, %1}, %2;" : "=f"(v.z), "=f"(v.w) : "l"(accA[2*q+1]));
        g_h[r0 * 16 + half * 8 + q] = v;
        p1a += v.x*aws[cb+4*q] + v.y*aws[cb+4*q+1] + v.z*aws[cb+4*q+2] + v.w*aws[cb+4*q+3];
        p2a += v.x*aws[64+cb+4*q] + v.y*aws[64+cb+4*q+1] + v.z*aws[64+cb+4*q+2] + v.w*aws[64+cb+4*q+3];
    }
    if (n1 < NN) {
        #pragma unroll
        for (int q = 0; q < 8; q++) {
            float4 v;
            asm("mov.b64 {%0, %1}, %2;" : "=f"(v.x), "=f"(v.y) : "l"(accB[2*q]));
            asm("mov.b64 {%0, %1}, %2;" : "=f"(v.z), "=f"(v.w) : "l"(accB[2*q+1]));
            g_h[(size_t)n1 * 16 + half * 8 + q] = v;
            p1b += v.x*aws[cb+4*q] + v.y*aws[cb+4*q+1] + v.z*aws[cb+4*q+2] + v.w*aws[cb+4*q+3];
            p2b += v.x*aws[64+cb+4*q] + v.y*aws[64+cb+4*q+1] + v.z*aws[64+cb+4*q+2] + v.w*aws[64+cb+4*q+3];
        }
    }
    // combine 2 column halves (adjacent lanes hold the same node pair)
    p1a += __shfl_xor_sync(0xffffffffu, p1a, 1);
    p2a += __shfl_xor_sync(0xffffffffu, p2a, 1);
    p1b += __shfl_xor_sync(0xffffffffu, p1b, 1);
    p2b += __shfl_xor_sync(0xffffffffu, p2b, 1);
    if (half == 0) {
        g_s1[n0] = p1a; g_s2[n0] = p2a;
        if (n1 < NN) { g_s1[n1] = p1b; g_s2[n1] = p2b; }
    }
}

// ---------------- grid barrier (all MB blocks co-resident) ----------------
__device__ __forceinline__ void gridsync(int p) {
    __syncthreads();
    if (threadIdx.x == 0) {
        __threadfence();
        atomicAdd(&g_bar[p], 1u);
        while (atomicAdd(&g_bar[p], 0u) < (unsigned)MB) { }
        __threadfence();
    }
    __syncthreads();
}

// ---------------- K2: fused count + scan + sort (persistent, 148 blocks) ----------------
__global__ void __launch_bounds__(MT)
k_mega(const int* __restrict__ eidx) {
    __shared__ int sm[MT];
    __shared__ float wr[MT / 32];
    const int b = blockIdx.x, t = threadIdx.x;
    const int gt = b * MT + t;
    const int nth = MB * MT;

    // phase A: destination histogram
    for (int e = gt; e < NE; e += nth)
        atomicAdd(&g_cnt[__ldg(eidx + e)], 1);
    gridsync(0);

    // phase B1: local exclusive scan of this block's MT nodes
    const int n = gt;
    int v = (n < NN) ? __ldcg(&g_cnt[n]) : 0;
    sm[t] = v;
    __syncthreads();
    #pragma unroll
    for (int off = 1; off < MT; off <<= 1) {
        int add = (t >= off) ? sm[t - off] : 0;
        __syncthreads();
        sm[t] += add;
        __syncthreads();
    }
    if (t == MT - 1) g_bsum[b] = sm[MT - 1];
    const int local_ex = sm[t] - v;
    gridsync(1);

    // phase B2: block 0 scans the 148 block sums
    if (b == 0) {
        int vv = (t < MB) ? __ldcg(&g_bsum[t]) : 0;
        sm[t] = vv;
        __syncthreads();
        #pragma unroll
        for (int off = 1; off < MT; off <<= 1) {
            int add = (t >= off) ? sm[t - off] : 0;
            __syncthreads();
            sm[t] += add;
            __syncthreads();
        }
        if (t < MB) g_bbase[t] = sm[t] - vv;
    }
    gridsync(2);

    // phase B3: write CSR offsets + cursors
    if (n < NN) {
        int o = __ldcg(&g_bbase[b]) + local_ex;
        g_off[n] = o;
        g_cur[n] = o;
    }
    gridsync(3);

    // phase C: fused expv + counting-sort + global sum
    float lsum = 0.f;
    for (int e = gt; e < NE; e += nth) {
        int i = __ldg(eidx + e);
        int j = __ldg(eidx + NE + e);
        float l = g_s1[i] + g_s2[j];
        l = (l > 0.f) ? l : 0.2f * l;       // leaky_relu 0.2
        float ex = __expf(l);
        lsum += ex;
        int pos = atomicAdd(&g_cur[i], 1);
        g_srt[pos] = make_int2(j, __float_as_int(ex));
    }
    #pragma unroll
    for (int o = 16; o > 0; o >>= 1) lsum += __shfl_down_sync(0xffffffffu, lsum, o);
    int w = t >> 5, lane = t & 31;
    if (lane == 0) wr[w] = lsum;
    __syncthreads();
    if (w == 0) {
        float s = (lane < MT / 32) ? wr[lane] : 0.f;
        #pragma unroll
        for (int o = 8; o > 0; o >>= 1) s += __shfl_down_sync(0xffffffffu, s, o);
        if (lane == 0) atomicAdd(&g_sum, s);
    }
}

// ---------------- K3: per-node gather (1 warp/node, 2 records in flight) ----------------
__global__ void k_gather(float* __restrict__ out) {
    int gt = blockIdx.x * blockDim.x + threadIdx.x;
    int lane = threadIdx.x & 31;
    int n = gt >> 5;
    if (n >= NN) return;
    int l16 = lane & 15;
    int sub = lane >> 4;

    float inv = 1.0f / g_sum;
    int beg = g_off[n];
    int cnt = g_cnt[n];

    float4 acc = make_float4(0.f, 0.f, 0.f, 0.f);
    int k = sub;
    int2 rec = (k < cnt) ? __ldg(&g_srt[beg + k]) : make_int2(0, 0);
    while (k < cnt) {
        int2 cur = rec;
        int kn = k + 2;
        if (kn < cnt) rec = __ldg(&g_srt[beg + kn]);
        float ex = __int_as_float(cur.y);
        float4 hv = g_h[(size_t)cur.x * 16 + l16];
        acc.x += hv.x * ex; acc.y += hv.y * ex;
        acc.z += hv.z * ex; acc.w += hv.w * ex;
        k = kn;
    }
    acc.x += __shfl_xor_sync(0xffffffffu, acc.x, 16);
    acc.y += __shfl_xor_sync(0xffffffffu, acc.y, 16);
    acc.z += __shfl_xor_sync(0xffffffffu, acc.z, 16);
    acc.w += __shfl_xor_sync(0xffffffffu, acc.w, 16);
    acc.x *= inv; acc.y *= inv; acc.z *= inv; acc.w *= inv;

    float4* o = (float4*)out + (size_t)n * 128;
    #pragma unroll
    for (int q = 0; q < 4; q++) o[lane + 32 * q] = acc;
}

extern "C" void kernel_launch(void* const* d_in, const int* in_sizes, int n_in,
                              void* d_out, int out_size) {
    const float* x    = (const float*)d_in[0];
    const int*   eidx = (const int*)d_in[1];
    const float* W    = (const float*)d_in[2];
    const float* attn = (const float*)d_in[3];
    float* out = (float*)d_out;

    k_gemm<<<GB, 128>>>(x, W, attn);
    k_mega<<<MB, MT>>>(eidx);
    k_gather<<<(NN * 32 + 255) / 256, 256>>>(out);
}

// round 17
// speedup vs baseline: 1.3131x; 1.0139x over previous
#include <cuda_runtime.h>
#include <math.h>

#define NN 50000
#define NE 800000
#define MB 148           // mega blocks: one per SM, all co-resident
#define MT 512           // mega threads per block
#define GB 391           // gemm blocks: 128-node tile each; 391*128 = 50048 >= NN

// ---- device scratch ----
__device__ float4 g_h[NN * 16];     // h = x@W, [NN,64] as float4
__device__ float  g_s1[NN];         // dot(h[n], a[:64])
__device__ float  g_s2[NN];         // dot(h[n], a[64:])
__device__ int    g_cnt[NN];        // in-degree
__device__ int    g_off[NN];        // exclusive prefix (CSR row start)
__device__ int    g_cur[NN];        // running cursor for sort
__device__ int2   g_srt[NE];        // sorted records: (src node j, expv bits)
__device__ int    g_bsum[MB];       // per-block sums
__device__ int    g_bbase[MB];      // exclusive scan of block sums
__device__ float  g_sum;            // sum of exp(logits)
__device__ unsigned g_bar[4];       // grid-barrier arrival counters

// ---------------- K1: h = x@W + per-node scores ----------------
// thread = (node pair, column half): 2 nodes x 32 cols, 32 f32x2 accs.
// x is STAGED through smem in 4 k-chunks (coalesced LDG, swizzled LDS) --
// removes the 32-lines-per-LDG gather that made all prior variants L1-bound.
__global__ void __launch_bounds__(128, 4)
k_gemm(const float* __restrict__ x,
       const float* __restrict__ W,
       const float* __restrict__ attn) {
    __shared__ ulonglong2 Ws2[2048];   // W [k*16 + c*2 + half], 32KB
    __shared__ float4 xs4[1024];       // 128 nodes x 8 float4 (swizzled), 16KB
    const int t = threadIdx.x;
    const int gt = blockIdx.x * 128 + t;

    // prologue: reset per-replay state (runs before k_mega in stream order)
    for (int i = gt; i < NN; i += GB * 128) g_cnt[i] = 0;
    if (gt == 0) {
        g_sum = 0.f;
        g_bar[0] = 0; g_bar[1] = 0; g_bar[2] = 0; g_bar[3] = 0;
    }

    {
        const float4* W4 = (const float4*)W;
        float4* Ws4 = (float4*)Ws2;
        // physical [k*16 + c*2 + half] <- logical chunk (k, half*8 + c)
        for (int p = t; p < 2048; p += 128) {
            int k = p >> 4, j = p & 15, c = j >> 1, hf = j & 1;
            Ws4[p] = W4[k * 16 + hf * 8 + c];
        }
    }

    const int slot = t >> 1;          // 0..63 node-pair slot
    const int half = t & 1;           // column half: cols [half*32, half*32+32)
    const int tile = blockIdx.x * 128;
    const int n0 = tile + slot * 2;
    const int n1 = n0 + 1;

    unsigned long long accA[16], accB[16];   // 32 cols per node as f32x2
    #pragma unroll
    for (int c = 0; c < 16; c++) { accA[c] = 0ull; accB[c] = 0ull; }

    const float4* x4 = (const float4*)x;
    const int sw = slot & 7;          // swizzle key: (node>>1)&7 for both rows

    #pragma unroll 1
    for (int kc = 0; kc < 4; kc++) {
        __syncthreads();              // xs4 free (also orders W fill on kc=0)
        // stage 128 nodes x 8 float4 (32 k values), coalesced + swizzled
        for (int i = t; i < 1024; i += 128) {
            int node = i >> 3, c8 = i & 7;
            int gn = tile + node;
            float4 v = make_float4(0.f, 0.f, 0.f, 0.f);
            if (gn < NN) v = x4[(size_t)gn * 32 + kc * 8 + c8];
            xs4[node * 8 + (c8 ^ ((node >> 1) & 7))] = v;
        }
        __syncthreads();

        #pragma unroll
        for (int k8 = 0; k8 < 8; k8++) {
            float4 xa = xs4[(slot * 2) * 8 + (k8 ^ sw)];
            float4 xb = xs4[(slot * 2 + 1) * 8 + (k8 ^ sw)];
            const int k4g = kc * 8 + k8;
            #pragma unroll
            for (int s = 0; s < 4; s++) {
                float fa = (s == 0) ? xa.x : (s == 1) ? xa.y : (s == 2) ? xa.z : xa.w;
                float fb = (s == 0) ? xb.x : (s == 1) ? xb.y : (s == 2) ? xb.z : xb.w;
                unsigned long long pa, pb;
                asm("mov.b64 %0, {%1, %1};" : "=l"(pa) : "f"(fa));
                asm("mov.b64 %0, {%1, %1};" : "=l"(pb) : "f"(fb));
                const ulonglong2* wk = Ws2 + (k4g * 4 + s) * 16 + half;
                #pragma unroll
                for (int c = 0; c < 8; c++) {
                    ulonglong2 wv = wk[c * 2];
                    asm("fma.rn.f32x2 %0, %1, %2, %0;" : "+l"(accA[2*c])   : "l"(pa), "l"(wv.x));
                    asm("fma.rn.f32x2 %0, %1, %2, %0;" : "+l"(accA[2*c+1]) : "l"(pa), "l"(wv.y));
                    asm("fma.rn.f32x2 %0, %1, %2, %0;" : "+l"(accB[2*c])   : "l"(pb), "l"(wv.x));
                    asm("fma.rn.f32x2 %0, %1, %2, %0;" : "+l"(accB[2*c+1]) : "l"(pb), "l"(wv.y));
                }
            }
        }
    }

    // stage attn weights into the (now free) x buffer
    __syncthreads();
    if (t < 32) xs4[t] = ((const float4*)attn)[t];
    __syncthreads();
    const float* aws = (const float*)xs4;

    const int cb = half * 32;         // this thread's column base
    float p1a = 0.f, p2a = 0.f, p1b = 0.f, p2b = 0.f;
    if (n0 < NN) {
        #pragma unroll
        for (int q = 0; q < 8; q++) {
            float4 v;
            asm("mov.b64 {%0, %1}, %2;" : "=f"(v.x), "=f"(v.y) : "l"(accA[2*q]));
            asm("mov.b64 {%0, %1}, %2;" : "=f"(v.z), "=f"(v.w) : "l"(accA[2*q+1]));
            g_h[(size_t)n0 * 16 + half * 8 + q] = v;
            p1a += v.x*aws[cb+4*q] + v.y*aws[cb+4*q+1] + v.z*aws[cb+4*q+2] + v.w*aws[cb+4*q+3];
            p2a += v.x*aws[64+cb+4*q] + v.y*aws[64+cb+4*q+1] + v.z*aws[64+cb+4*q+2] + v.w*aws[64+cb+4*q+3];
        }
    }
    if (n1 < NN) {
        #pragma unroll
        for (int q = 0; q < 8; q++) {
            float4 v;
            asm("mov.b64 {%0, %1}, %2;" : "=f"(v.x), "=f"(v.y) : "l"(accB[2*q]));
            asm("mov.b64 {%0, %1}, %2;" : "=f"(v.z), "=f"(v.w) : "l"(accB[2*q+1]));
            g_h[(size_t)n1 * 16 + half * 8 + q] = v;
            p1b += v.x*aws[cb+4*q] + v.y*aws[cb+4*q+1] + v.z*aws[cb+4*q+2] + v.w*aws[cb+4*q+3];
            p2b += v.x*aws[64+cb+4*q] + v.y*aws[64+cb+4*q+1] + v.z*aws[64+cb+4*q+2] + v.w*aws[64+cb+4*q+3];
        }
    }
    // combine 2 column halves (adjacent lanes hold the same node pair)
    p1a += __shfl_xor_sync(0xffffffffu, p1a, 1);
    p2a += __shfl_xor_sync(0xffffffffu, p2a, 1);
    p1b += __shfl_xor_sync(0xffffffffu, p1b, 1);
    p2b += __shfl_xor_sync(0xffffffffu, p2b, 1);
    if (half == 0 && n0 < NN) {
        g_s1[n0] = p1a; g_s2[n0] = p2a;
        if (n1 < NN) { g_s1[n1] = p1b; g_s2[n1] = p2b; }
    }
}

// ---------------- grid barrier (all MB blocks co-resident) ----------------
__device__ __forceinline__ void gridsync(int p) {
    __syncthreads();
    if (threadIdx.x == 0) {
        __threadfence();
        atomicAdd(&g_bar[p], 1u);
        while (atomicAdd(&g_bar[p], 0u) < (unsigned)MB) { }
        __threadfence();
    }
    __syncthreads();
}

// ---------------- K2: fused count + scan + sort (persistent, 148 blocks) ----------------
__global__ void __launch_bounds__(MT)
k_mega(const int* __restrict__ eidx) {
    __shared__ int sm[MT];
    __shared__ float wr[MT / 32];
    const int b = blockIdx.x, t = threadIdx.x;
    const int gt = b * MT + t;
    const int nth = MB * MT;

    // phase A: destination histogram
    for (int e = gt; e < NE; e += nth)
        atomicAdd(&g_cnt[__ldg(eidx + e)], 1);
    gridsync(0);

    // phase B1: local exclusive scan of this block's MT nodes
    const int n = gt;
    int v = (n < NN) ? __ldcg(&g_cnt[n]) : 0;
    sm[t] = v;
    __syncthreads();
    #pragma unroll
    for (int off = 1; off < MT; off <<= 1) {
        int add = (t >= off) ? sm[t - off] : 0;
        __syncthreads();
        sm[t] += add;
        __syncthreads();
    }
    if (t == MT - 1) g_bsum[b] = sm[MT - 1];
    const int local_ex = sm[t] - v;
    gridsync(1);

    // phase B2: block 0 scans the 148 block sums
    if (b == 0) {
        int vv = (t < MB) ? __ldcg(&g_bsum[t]) : 0;
        sm[t] = vv;
        __syncthreads();
        #pragma unroll
        for (int off = 1; off < MT; off <<= 1) {
            int add = (t >= off) ? sm[t - off] : 0;
            __syncthreads();
            sm[t] += add;
            __syncthreads();
        }
        if (t < MB) g_bbase[t] = sm[t] - vv;
    }
    gridsync(2);

    // phase B3: write CSR offsets + cursors
    if (n < NN) {
        int o = __ldcg(&g_bbase[b]) + local_ex;
        g_off[n] = o;
        g_cur[n] = o;
    }
    gridsync(3);

    // phase C: fused expv + counting-sort + global sum
    float lsum = 0.f;
    for (int e = gt; e < NE; e += nth) {
        int i = __ldg(eidx + e);
        int j = __ldg(eidx + NE + e);
        float l = g_s1[i] + g_s2[j];
        l = (l > 0.f) ? l : 0.2f * l;       // leaky_relu 0.2
        float ex = __expf(l);
        lsum += ex;
        int pos = atomicAdd(&g_cur[i], 1);
        g_srt[pos] = make_int2(j, __float_as_int(ex));
    }
    #pragma unroll
    for (int o = 16; o > 0; o >>= 1) lsum += __shfl_down_sync(0xffffffffu, lsum, o);
    int w = t >> 5, lane = t & 31;
    if (lane == 0) wr[w] = lsum;
    __syncthreads();
    if (w == 0) {
        float s = (lane < MT / 32) ? wr[lane] : 0.f;
        #pragma unroll
        for (int o = 8; o > 0; o >>= 1) s += __shfl_down_sync(0xffffffffu, s, o);
        if (lane == 0) atomicAdd(&g_sum, s);
    }
}

// ---------------- K3: per-node gather (1 warp/node, 2 records in flight) ----------------
__global__ void k_gather(float* __restrict__ out) {
    int gt = blockIdx.x * blockDim.x + threadIdx.x;
    int lane = threadIdx.x & 31;
    int n = gt >> 5;
    if (n >= NN) return;
    int l16 = lane & 15;
    int sub = lane >> 4;

    float inv = 1.0f / g_sum;
    int beg = g_off[n];
    int cnt = g_cnt[n];

    float4 acc = make_float4(0.f, 0.f, 0.f, 0.f);
    int k = sub;
    int2 rec = (k < cnt) ? __ldg(&g_srt[beg + k]) : make_int2(0, 0);
    while (k < cnt) {
        int2 cur = rec;
        int kn = k + 2;
        if (kn < cnt) rec = __ldg(&g_srt[beg + kn]);
        float ex = __int_as_float(cur.y);
        float4 hv = g_h[(size_t)cur.x * 16 + l16];
        acc.x += hv.x * ex; acc.y += hv.y * ex;
        acc.z += hv.z * ex; acc.w += hv.w * ex;
        k = kn;
    }
    acc.x += __shfl_xor_sync(0xffffffffu, acc.x, 16);
    acc.y += __shfl_xor_sync(0xffffffffu, acc.y, 16);
    acc.z += __shfl_xor_sync(0xffffffffu, acc.z, 16);
    acc.w += __shfl_xor_sync(0xffffffffu, acc.w, 16);
    acc.x *= inv; acc.y *= inv; acc.z *= inv; acc.w *= inv;

    float4* o = (float4*)out + (size_t)n * 128;
    #pragma unroll
    for (int q = 0; q < 4; q++) o[lane + 32 * q] = acc;
}

extern "C" void kernel_launch(void* const* d_in, const int* in_sizes, int n_in,
                              void* d_out, int out_size) {
    const float* x    = (const float*)d_in[0];
    const int*   eidx = (const int*)d_in[1];
    const float* W    = (const float*)d_in[2];
    const float* attn = (const float*)d_in[3];
    float* out = (float*)d_out;

    k_gemm<<<GB, 128>>>(x, W, attn);
    k_mega<<<MB, MT>>>(eidx);
    k_gather<<<(NN * 32 + 255) / 256, 256>>>(out);
}